// round 8
// baseline (speedup 1.0000x reference)
#include <cuda_runtime.h>
#include <cuda_bf16.h>
#include <cstdint>

// Problem constants (fixed by the reference)
#define NN       100000
#define IN_F     128
#define HH       4
#define DD       32
#define HD       128          // H*D
#define RR       3
#define EE       800000
#define NEG_SLOPE 0.2f
#define KP       136          // padded K stride (272B rows, conflict-free LDS)

#define SCAN_N   (RR * NN)                 // 300000
#define SCAN_NB  ((SCAN_N + 1023) / 1024)  // 293

// ---------------------------------------------------------------------------
// Scratch (device globals — no allocation APIs allowed)
// ---------------------------------------------------------------------------
__device__ __align__(256) float g_FS[RR * NN * HD];
__device__ __align__(256) float g_FD[RR * NN * HD];
__device__ __align__(256) float g_NUM[RR * NN * HD];   // normalized per-relation output
__device__ __align__(256) __nv_bfloat16 g_Hhi[NN * IN_F];
__device__ __align__(256) __nv_bfloat16 g_Hlo[NN * IN_F];
__device__ __align__(256) __nv_bfloat16 g_Whi[6 * HD * IN_F];  // [m2][n][k]
__device__ __align__(256) __nv_bfloat16 g_Wlo[6 * HD * IN_F];
// CSR machinery
__device__ int g_cnt[SCAN_N];
__device__ int g_cur[SCAN_N];
__device__ int g_off[SCAN_N + 1];
__device__ int g_bsum[SCAN_NB + 8];
__device__ int g_esrc[RR * EE];

// ---------------------------------------------------------------------------
// Zero histogram + cursors (tiny)
// ---------------------------------------------------------------------------
__global__ void zero_kernel() {
    int stride = gridDim.x * blockDim.x;
    int tid = blockIdx.x * blockDim.x + threadIdx.x;
    for (int i = tid; i < SCAN_N; i += stride) { g_cnt[i] = 0; g_cur[i] = 0; }
}

// ---------------------------------------------------------------------------
// Split h into bf16 hi/lo
// ---------------------------------------------------------------------------
__global__ void split_h_kernel(const float* __restrict__ h) {
    int stride = gridDim.x * blockDim.x;
    int tid = blockIdx.x * blockDim.x + threadIdx.x;
    const int total4 = (NN * IN_F) / 4;
    for (int i = tid; i < total4; i += stride) {
        float4 v = reinterpret_cast<const float4*>(h)[i];
        __nv_bfloat16 hi[4], lo[4];
        float xs[4] = {v.x, v.y, v.z, v.w};
#pragma unroll
        for (int j = 0; j < 4; j++) {
            hi[j] = __float2bfloat16(xs[j]);
            lo[j] = __float2bfloat16(xs[j] - __bfloat162float(hi[j]));
        }
        reinterpret_cast<uint2*>(g_Hhi)[i] = *reinterpret_cast<uint2*>(hi);
        reinterpret_cast<uint2*>(g_Hlo)[i] = *reinterpret_cast<uint2*>(lo);
    }
}

// Split + transpose W:  g_W*[m2][n][k] = W[m2][k][n]
__global__ void split_w_kernel(const float* __restrict__ Wsrc,
                               const float* __restrict__ Wdst) {
    int i = blockIdx.x * blockDim.x + threadIdx.x;
    if (i >= 6 * HD * IN_F) return;
    int m2 = i >> 14;
    int rem = i & 16383;
    int n = rem >> 7;
    int k = rem & 127;
    const float* W = (m2 < 3) ? (Wsrc + (size_t)m2 * IN_F * HD)
                              : (Wdst + (size_t)(m2 - 3) * IN_F * HD);
    float x = W[k * HD + n];
    __nv_bfloat16 hi = __float2bfloat16(x);
    __nv_bfloat16 lo = __float2bfloat16(x - __bfloat162float(hi));
    g_Whi[i] = hi;
    g_Wlo[i] = lo;
}

// ---------------------------------------------------------------------------
// CSR build: histogram -> 3-kernel exclusive scan -> scatter
// ---------------------------------------------------------------------------
__global__ void hist_kernel(const int* __restrict__ dst) {
    int i = blockIdx.x * blockDim.x + threadIdx.x;
    if (i >= RR * EE) return;
    int r = i / EE;
    atomicAdd(&g_cnt[r * NN + dst[i]], 1);
}

__global__ void scan1_kernel() {   // 293 blocks x 1024
    __shared__ int ws[32];
    int i = blockIdx.x * 1024 + threadIdx.x;
    int v = (i < SCAN_N) ? g_cnt[i] : 0;
    int lane = threadIdx.x & 31, w = threadIdx.x >> 5;
    int x = v;
#pragma unroll
    for (int o = 1; o < 32; o <<= 1) { int y = __shfl_up_sync(~0u, x, o); if (lane >= o) x += y; }
    if (lane == 31) ws[w] = x;
    __syncthreads();
    if (w == 0) {
        int y = ws[lane];
#pragma unroll
        for (int o = 1; o < 32; o <<= 1) { int z = __shfl_up_sync(~0u, y, o); if (lane >= o) y += z; }
        ws[lane] = y;
    }
    __syncthreads();
    int base = (w > 0) ? ws[w - 1] : 0;
    int incl = x + base;
    if (i < SCAN_N) g_off[i] = incl - v;          // exclusive within block
    if (threadIdx.x == 1023) g_bsum[blockIdx.x] = incl;  // block total
}

__global__ void scan2_kernel() {   // 1 block x 512, scans SCAN_NB block sums
    __shared__ int ws[16];
    int i = threadIdx.x;
    int v = (i < SCAN_NB) ? g_bsum[i] : 0;
    int lane = i & 31, w = i >> 5;
    int x = v;
#pragma unroll
    for (int o = 1; o < 32; o <<= 1) { int y = __shfl_up_sync(~0u, x, o); if (lane >= o) x += y; }
    if (lane == 31) ws[w] = x;
    __syncthreads();
    if (w == 0) {
        int y = (lane < 16) ? ws[lane] : 0;
#pragma unroll
        for (int o = 1; o < 32; o <<= 1) { int z = __shfl_up_sync(~0u, y, o); if (lane >= o) y += z; }
        if (lane < 16) ws[lane] = y;
    }
    __syncthreads();
    int base = (w > 0) ? ws[w - 1] : 0;
    int incl = x + base;
    if (i < SCAN_NB) g_bsum[i] = incl - v;        // exclusive block offsets
}

__global__ void scan3_kernel() {   // add block offsets
    int i = blockIdx.x * 1024 + threadIdx.x;
    if (i < SCAN_N) g_off[i] += g_bsum[blockIdx.x];
    if (i == 0) g_off[SCAN_N] = RR * EE;
}

__global__ void scatter_kernel(const int* __restrict__ src,
                               const int* __restrict__ dst) {
    int i = blockIdx.x * blockDim.x + threadIdx.x;
    if (i >= RR * EE) return;
    int r = i / EE;
    int ni = r * NN + dst[i];
    int pos = g_off[ni] + atomicAdd(&g_cur[ni], 1);
    g_esrc[pos] = src[i];
}

// ---------------------------------------------------------------------------
// GEMM: persistent-A, double-buffered B prefetch, 3-pass split-bf16 mma.sync
// Grid = 782 M-tiles; each block computes all 6 weight matrices for its tile.
// smem: A(hi,lo) + 2 x B(hi,lo) = 208896 bytes.
// ---------------------------------------------------------------------------
#define TILE_BYTES 34816            // 128 * KP * 2
#define SMEM_A_HI  0
#define SMEM_A_LO  34816
#define SMEM_B0    69632
#define SMEM_B1    139264
#define GEMM_SMEM  208896

__device__ __forceinline__ void cp16(uint32_t smem, const void* g) {
    asm volatile("cp.async.cg.shared.global [%0], [%1], 16;\n" :: "r"(smem), "l"(g));
}
#define CPCOMMIT() asm volatile("cp.async.commit_group;\n" ::: "memory")
#define CPWAIT(N)  asm volatile("cp.async.wait_group %0;\n" :: "n"(N) : "memory")

__device__ __forceinline__ void mma_bf16(float d[4], const uint32_t a[4],
                                         const uint32_t b[2]) {
    asm volatile(
        "mma.sync.aligned.m16n8k16.row.col.f32.bf16.bf16.f32 "
        "{%0,%1,%2,%3},{%4,%5,%6,%7},{%8,%9},{%0,%1,%2,%3};"
        : "+f"(d[0]), "+f"(d[1]), "+f"(d[2]), "+f"(d[3])
        : "r"(a[0]), "r"(a[1]), "r"(a[2]), "r"(a[3]), "r"(b[0]), "r"(b[1]));
}

__device__ __forceinline__ void load_B(uint32_t smem_base, int m2, int tid) {
    const char* Wh = (const char*)(g_Whi + (size_t)m2 * HD * IN_F);
    const char* Wl = (const char*)(g_Wlo + (size_t)m2 * HD * IN_F);
#pragma unroll
    for (int it = 0; it < 8; it++) {
        int idx = it * 256 + tid;            // 0..2047 chunks of 16B
        int row = idx >> 4, c = idx & 15;
        cp16(smem_base + row * 272 + c * 16, Wh + row * 256 + c * 16);
    }
#pragma unroll
    for (int it = 0; it < 8; it++) {
        int idx = it * 256 + tid;
        int row = idx >> 4, c = idx & 15;
        cp16(smem_base + TILE_BYTES + row * 272 + c * 16, Wl + row * 256 + c * 16);
    }
}

__global__ void __launch_bounds__(256, 1)
gemm_kernel(const float* __restrict__ bsrc, const float* __restrict__ bdst) {
    extern __shared__ char smx[];
    uint32_t sb = (uint32_t)__cvta_generic_to_shared(smx);
    const int tid = threadIdx.x;
    const int m0 = blockIdx.x * 128;

    // ---- A tile (hi+lo), loaded once; tail rows zero-filled ----
#pragma unroll
    for (int it = 0; it < 8; it++) {
        int idx = it * 256 + tid;
        int row = idx >> 4, c = idx & 15;
        int grow = m0 + row;
        if (grow < NN) {
            cp16(sb + SMEM_A_HI + row * 272 + c * 16,
                 (const char*)g_Hhi + (size_t)grow * 256 + c * 16);
            cp16(sb + SMEM_A_LO + row * 272 + c * 16,
                 (const char*)g_Hlo + (size_t)grow * 256 + c * 16);
        } else {
            *reinterpret_cast<uint4*>(smx + SMEM_A_HI + row * 272 + c * 16) = make_uint4(0,0,0,0);
            *reinterpret_cast<uint4*>(smx + SMEM_A_LO + row * 272 + c * 16) = make_uint4(0,0,0,0);
        }
    }
    load_B(sb + SMEM_B0, 0, tid);
    CPCOMMIT();                 // G0 = A + B0
    load_B(sb + SMEM_B1, 1, tid);
    CPCOMMIT();                 // G1 = B1

    const int w = tid >> 5, lane = tid & 31;
    const int wm = w >> 2, wn = w & 3;
    const int g = lane >> 2, t = lane & 3;

    const __nv_bfloat16* A_hi = (const __nv_bfloat16*)(smx + SMEM_A_HI);
    const __nv_bfloat16* A_lo = (const __nv_bfloat16*)(smx + SMEM_A_LO);

#pragma unroll 1
    for (int m2 = 0; m2 < 6; m2++) {
        if (m2 < 5) { CPWAIT(1); } else { CPWAIT(0); }
        __syncthreads();

        const char* bbuf = smx + ((m2 & 1) ? SMEM_B1 : SMEM_B0);
        const __nv_bfloat16* B_hi = (const __nv_bfloat16*)bbuf;
        const __nv_bfloat16* B_lo = (const __nv_bfloat16*)(bbuf + TILE_BYTES);

        float acc[4][4][4];
#pragma unroll
        for (int mi = 0; mi < 4; mi++)
#pragma unroll
            for (int ni = 0; ni < 4; ni++)
#pragma unroll
                for (int j = 0; j < 4; j++) acc[mi][ni][j] = 0.f;

#pragma unroll
        for (int s = 0; s < 3; s++) {
            const __nv_bfloat16* Ab = (s == 1) ? A_lo : A_hi;
            const __nv_bfloat16* Bb = (s == 2) ? B_lo : B_hi;
#pragma unroll
            for (int k0 = 0; k0 < 128; k0 += 16) {
                uint32_t afr[4][4];
#pragma unroll
                for (int mi = 0; mi < 4; mi++) {
                    const __nv_bfloat16* ap = Ab + (wm * 64 + mi * 16 + g) * KP + k0;
                    afr[mi][0] = *reinterpret_cast<const uint32_t*>(ap + 2 * t);
                    afr[mi][1] = *reinterpret_cast<const uint32_t*>(ap + 8 * KP + 2 * t);
                    afr[mi][2] = *reinterpret_cast<const uint32_t*>(ap + 2 * t + 8);
                    afr[mi][3] = *reinterpret_cast<const uint32_t*>(ap + 8 * KP + 2 * t + 8);
                }
                uint32_t bfr[4][2];
#pragma unroll
                for (int ni = 0; ni < 4; ni++) {
                    const __nv_bfloat16* bp = Bb + (wn * 32 + ni * 8 + g) * KP + k0;
                    bfr[ni][0] = *reinterpret_cast<const uint32_t*>(bp + 2 * t);
                    bfr[ni][1] = *reinterpret_cast<const uint32_t*>(bp + 2 * t + 8);
                }
#pragma unroll
                for (int mi = 0; mi < 4; mi++)
#pragma unroll
                    for (int ni = 0; ni < 4; ni++)
                        mma_bf16(acc[mi][ni], afr[mi], bfr[ni]);
            }
        }

        // epilogue for this m2
        const int rr = (m2 < 3) ? m2 : m2 - 3;
        float* OUT = (m2 < 3) ? g_FS : g_FD;
        const float* bias = (m2 < 3) ? (bsrc + rr * HD) : (bdst + rr * HD);
#pragma unroll
        for (int mi = 0; mi < 4; mi++) {
#pragma unroll
            for (int ni = 0; ni < 4; ni++) {
                int row0 = m0 + wm * 64 + mi * 16 + g;
                int col = wn * 32 + ni * 8 + 2 * t;
                float b0 = bias[col], b1 = bias[col + 1];
                if (row0 < NN) {
                    float2 v = make_float2(acc[mi][ni][0] + b0, acc[mi][ni][1] + b1);
                    *reinterpret_cast<float2*>(&OUT[((size_t)rr * NN + row0) * HD + col]) = v;
                }
                if (row0 + 8 < NN) {
                    float2 v = make_float2(acc[mi][ni][2] + b0, acc[mi][ni][3] + b1);
                    *reinterpret_cast<float2*>(&OUT[((size_t)rr * NN + row0 + 8) * HD + col]) = v;
                }
            }
        }

        __syncthreads();                       // everyone done reading buf[m2&1]
        if (m2 + 2 < 6) {                      // prefetch B[m2+2] into freed buf
            load_B(sb + ((m2 & 1) ? SMEM_B1 : SMEM_B0), m2 + 2, tid);
            CPCOMMIT();
        }
    }
}

// ---------------------------------------------------------------------------
// CSR accumulation: one warp per (relation, dst-node).
// fd loaded once; fs gathered per in-edge; softmax normalized in registers.
// Unshifted exp is exact-safe (|logit| <~ 6) and identical after normalize.
// ---------------------------------------------------------------------------
__global__ void __launch_bounds__(256) accum_kernel(const float* __restrict__ attn) {
    int flat = (blockIdx.x * blockDim.x + threadIdx.x) >> 5;
    if (flat >= SCAN_N) return;
    const int lane = threadIdx.x & 31;
    const int r = flat / NN;
    const int n = flat - r * NN;

    const float4 av = *reinterpret_cast<const float4*>(attn + r * HD + lane * 4);
    const float* FSr = g_FS + (size_t)r * NN * HD;
    const float4 fdv = *reinterpret_cast<const float4*>(
        g_FD + ((size_t)r * NN + n) * HD + lane * 4);

    const int b = g_off[flat], e_end = g_off[flat + 1];
    float a0 = 0.f, a1 = 0.f, a2 = 0.f, a3 = 0.f, den = 0.f;

    for (int e = b; e < e_end; e++) {
        int s = __ldg(g_esrc + e);
        float4 fsv = __ldg(reinterpret_cast<const float4*>(FSr + (size_t)s * HD + lane * 4));
        float x0 = fsv.x + fdv.x; x0 = (x0 > 0.f) ? x0 : NEG_SLOPE * x0;
        float x1 = fsv.y + fdv.y; x1 = (x1 > 0.f) ? x1 : NEG_SLOPE * x1;
        float x2 = fsv.z + fdv.z; x2 = (x2 > 0.f) ? x2 : NEG_SLOPE * x2;
        float x3 = fsv.w + fdv.w; x3 = (x3 > 0.f) ? x3 : NEG_SLOPE * x3;
        float p = x0 * av.x + x1 * av.y + x2 * av.z + x3 * av.w;
        p += __shfl_xor_sync(0xffffffffu, p, 1);
        p += __shfl_xor_sync(0xffffffffu, p, 2);
        p += __shfl_xor_sync(0xffffffffu, p, 4);
        float ex = __expf(p);
        den += ex;
        a0 += fsv.x * ex; a1 += fsv.y * ex; a2 += fsv.z * ex; a3 += fsv.w * ex;
    }

    float4 o = make_float4(0.f, 0.f, 0.f, 0.f);
    if (e_end > b) {
        float inv = 1.f / den;
        o = make_float4(a0 * inv, a1 * inv, a2 * inv, a3 * inv);
    }
    *reinterpret_cast<float4*>(g_NUM + ((size_t)r * NN + n) * HD + lane * 4) = o;
}

// ---------------------------------------------------------------------------
// Finalize: out = sum_r NUM_r + sum_r bias_r
// ---------------------------------------------------------------------------
__global__ void finalize_kernel(const float* __restrict__ bias,
                                float* __restrict__ out) {
    int stride = gridDim.x * blockDim.x;
    int tid = blockIdx.x * blockDim.x + threadIdx.x;
    const int total4 = NN * (HD / 4);
    for (int i = tid; i < total4; i += stride) {
        int n = i >> 5;
        int c = (i & 31) * 4;
        float4 acc;
        acc.x = bias[c]     + bias[HD + c]     + bias[2 * HD + c];
        acc.y = bias[c + 1] + bias[HD + c + 1] + bias[2 * HD + c + 1];
        acc.z = bias[c + 2] + bias[HD + c + 2] + bias[2 * HD + c + 2];
        acc.w = bias[c + 3] + bias[HD + c + 3] + bias[2 * HD + c + 3];
#pragma unroll
        for (int r = 0; r < RR; r++) {
            const float4 v = *reinterpret_cast<const float4*>(
                g_NUM + ((size_t)r * NN + n) * HD + c);
            acc.x += v.x; acc.y += v.y; acc.z += v.z; acc.w += v.w;
        }
        reinterpret_cast<float4*>(out)[i] = acc;
    }
}

// ---------------------------------------------------------------------------
// Launcher
// ---------------------------------------------------------------------------
extern "C" void kernel_launch(void* const* d_in, const int* in_sizes, int n_in,
                              void* d_out, int out_size) {
    (void)in_sizes; (void)n_in; (void)out_size;
    const float* h     = (const float*)d_in[0];
    const float* W_src = (const float*)d_in[1];
    const float* b_src = (const float*)d_in[2];
    const float* W_dst = (const float*)d_in[3];
    const float* b_dst = (const float*)d_in[4];
    const float* attn  = (const float*)d_in[5];
    const float* bias  = (const float*)d_in[6];
    const int* src_idx = (const int*)d_in[7];
    const int* dst_idx = (const int*)d_in[8];
    float* out = (float*)d_out;

    cudaFuncSetAttribute(gemm_kernel, cudaFuncAttributeMaxDynamicSharedMemorySize,
                         GEMM_SMEM);

    const int eb = (RR * EE + 255) / 256;      // 9375

    zero_kernel<<<592, 256>>>();
    split_h_kernel<<<1480, 256>>>(h);
    split_w_kernel<<<(6 * HD * IN_F + 255) / 256, 256>>>(W_src, W_dst);
    hist_kernel<<<eb, 256>>>(dst_idx);
    scan1_kernel<<<SCAN_NB, 1024>>>();
    scan2_kernel<<<1, 512>>>();
    scan3_kernel<<<SCAN_NB, 1024>>>();
    scatter_kernel<<<eb, 256>>>(src_idx, dst_idx);
    gemm_kernel<<<(NN + 127) / 128, 256, GEMM_SMEM>>>(b_src, b_dst);
    accum_kernel<<<SCAN_N / 8, 256>>>(attn);
    finalize_kernel<<<1480, 256>>>(bias, out);
}